// round 1
// baseline (speedup 1.0000x reference)
#include <cuda_runtime.h>
#include <cstddef>
#include <math.h>

#define G_    8192
#define IND_  512
#define KQD_  128
#define OUTD_ 512

// Scratch (static __device__ arrays are the allowed scratch mechanism)
__device__ float g_k[(size_t)G_ * KQD_];
__device__ float g_q[(size_t)G_ * KQD_];
__device__ float g_v[(size_t)G_ * OUTD_];
__device__ float g_scores[(size_t)G_ * G_];
__device__ float g_rinv[G_];

// ---------------------------------------------------------------------------
// GEMM NT:  C[M,N] = A[M,K] @ B[N,K]^T (+ bias[N] if bias != nullptr)
// Block tile 128x128, K-tile 16, 256 threads, 8x8 per-thread microtile.
// All of M,N divisible by 128; K divisible by 16. No bounds checks.
// ---------------------------------------------------------------------------
__global__ __launch_bounds__(256, 2)
void gemm_nt_kernel(const float* __restrict__ A, const float* __restrict__ B,
                    const float* __restrict__ bias, float* __restrict__ C,
                    int M, int N, int K)
{
    __shared__ float As[16][128];
    __shared__ float Bs[16][128];

    const int tid = threadIdx.x;
    const int tx  = tid & 15;          // 0..15 -> column group
    const int ty  = tid >> 4;          // 0..15 -> row group
    const int rowBase = blockIdx.y * 128;
    const int colBase = blockIdx.x * 128;

    float acc[8][8];
#pragma unroll
    for (int i = 0; i < 8; i++)
#pragma unroll
        for (int j = 0; j < 8; j++) acc[i][j] = 0.f;

    for (int k0 = 0; k0 < K; k0 += 16) {
        // Load A tile: 128 rows x 16 k  (512 float4, 2 per thread)
#pragma unroll
        for (int l = 0; l < 2; l++) {
            int idx = tid + l * 256;
            int r  = idx >> 2;
            int kc = (idx & 3) * 4;
            float4 v = *reinterpret_cast<const float4*>(
                &A[(size_t)(rowBase + r) * K + k0 + kc]);
            As[kc + 0][r] = v.x; As[kc + 1][r] = v.y;
            As[kc + 2][r] = v.z; As[kc + 3][r] = v.w;
        }
        // Load B tile (B is [N,K] row-major): 128 cols x 16 k
#pragma unroll
        for (int l = 0; l < 2; l++) {
            int idx = tid + l * 256;
            int r  = idx >> 2;
            int kc = (idx & 3) * 4;
            float4 v = *reinterpret_cast<const float4*>(
                &B[(size_t)(colBase + r) * K + k0 + kc]);
            Bs[kc + 0][r] = v.x; Bs[kc + 1][r] = v.y;
            Bs[kc + 2][r] = v.z; Bs[kc + 3][r] = v.w;
        }
        __syncthreads();

#pragma unroll
        for (int kk = 0; kk < 16; kk++) {
            float a[8], b[8];
#pragma unroll
            for (int i = 0; i < 8; i++) a[i] = As[kk][ty * 8 + i];
#pragma unroll
            for (int j = 0; j < 8; j++) b[j] = Bs[kk][tx * 8 + j];
#pragma unroll
            for (int i = 0; i < 8; i++)
#pragma unroll
                for (int j = 0; j < 8; j++)
                    acc[i][j] += a[i] * b[j];
        }
        __syncthreads();
    }

#pragma unroll
    for (int i = 0; i < 8; i++) {
        int row = rowBase + ty * 8 + i;
#pragma unroll
        for (int jj = 0; jj < 8; jj += 4) {
            int col = colBase + tx * 8 + jj;
            float4 o;
            if (bias != nullptr) {
                o.x = acc[i][jj + 0] + bias[col + 0];
                o.y = acc[i][jj + 1] + bias[col + 1];
                o.z = acc[i][jj + 2] + bias[col + 2];
                o.w = acc[i][jj + 3] + bias[col + 3];
            } else {
                o.x = acc[i][jj + 0]; o.y = acc[i][jj + 1];
                o.z = acc[i][jj + 2]; o.w = acc[i][jj + 3];
            }
            *reinterpret_cast<float4*>(&C[(size_t)row * N + col]) = o;
        }
    }
}

// ---------------------------------------------------------------------------
// Per-row 1/max(||row||_2, eps) of the scores matrix
// ---------------------------------------------------------------------------
__global__ void rownorm_kernel(const float* __restrict__ S, float* __restrict__ rinv)
{
    const int row = blockIdx.x;
    const float4* p = reinterpret_cast<const float4*>(S + (size_t)row * G_);
    float s = 0.f;
    for (int j = threadIdx.x; j < G_ / 4; j += blockDim.x) {
        float4 v = p[j];
        s += v.x * v.x + v.y * v.y + v.z * v.z + v.w * v.w;
    }
#pragma unroll
    for (int o = 16; o > 0; o >>= 1) s += __shfl_xor_sync(0xffffffffu, s, o);

    __shared__ float red[8];
    if ((threadIdx.x & 31) == 0) red[threadIdx.x >> 5] = s;
    __syncthreads();
    if (threadIdx.x < 8) {
        s = red[threadIdx.x];
#pragma unroll
        for (int o = 4; o > 0; o >>= 1) s += __shfl_xor_sync(0xffu, s, o);
        if (threadIdx.x == 0)
            rinv[row] = 1.0f / fmaxf(sqrtf(s), 1e-12f);
    }
}

// ---------------------------------------------------------------------------
// GEMM NN with fused epilogue:
//   out[i, o] = rinv[i] * (S[i,:] @ V[:,o]) + V[i, o]
// S: [G, G] row-major, V: [G, OUTD] row-major.
// ---------------------------------------------------------------------------
__global__ __launch_bounds__(256, 2)
void gemm_nn_out_kernel(const float* __restrict__ S, const float* __restrict__ V,
                        const float* __restrict__ rinv, float* __restrict__ C)
{
    __shared__ float As[16][128];
    __shared__ float Bs[16][128];

    const int tid = threadIdx.x;
    const int tx  = tid & 15;
    const int ty  = tid >> 4;
    const int rowBase = blockIdx.y * 128;
    const int colBase = blockIdx.x * 128;

    float acc[8][8];
#pragma unroll
    for (int i = 0; i < 8; i++)
#pragma unroll
        for (int j = 0; j < 8; j++) acc[i][j] = 0.f;

    for (int k0 = 0; k0 < G_; k0 += 16) {
        // S tile: 128 rows x 16 k
#pragma unroll
        for (int l = 0; l < 2; l++) {
            int idx = tid + l * 256;
            int r  = idx >> 2;
            int kc = (idx & 3) * 4;
            float4 v = *reinterpret_cast<const float4*>(
                &S[(size_t)(rowBase + r) * G_ + k0 + kc]);
            As[kc + 0][r] = v.x; As[kc + 1][r] = v.y;
            As[kc + 2][r] = v.z; As[kc + 3][r] = v.w;
        }
        // V tile: 16 k-rows x 128 cols, direct coalesced float4 copy
#pragma unroll
        for (int l = 0; l < 2; l++) {
            int idx = tid + l * 256;
            int kk = idx >> 5;
            int c4 = (idx & 31) * 4;
            *reinterpret_cast<float4*>(&Bs[kk][c4]) =
                *reinterpret_cast<const float4*>(
                    &V[(size_t)(k0 + kk) * OUTD_ + colBase + c4]);
        }
        __syncthreads();

#pragma unroll
        for (int kk = 0; kk < 16; kk++) {
            float a[8], b[8];
#pragma unroll
            for (int i = 0; i < 8; i++) a[i] = As[kk][ty * 8 + i];
#pragma unroll
            for (int j = 0; j < 8; j++) b[j] = Bs[kk][tx * 8 + j];
#pragma unroll
            for (int i = 0; i < 8; i++)
#pragma unroll
                for (int j = 0; j < 8; j++)
                    acc[i][j] += a[i] * b[j];
        }
        __syncthreads();
    }

#pragma unroll
    for (int i = 0; i < 8; i++) {
        int row = rowBase + ty * 8 + i;
        float rv = rinv[row];
#pragma unroll
        for (int jj = 0; jj < 8; jj += 4) {
            int col = colBase + tx * 8 + jj;
            float4 res = *reinterpret_cast<const float4*>(
                &V[(size_t)row * OUTD_ + col]);
            float4 o;
            o.x = rv * acc[i][jj + 0] + res.x;
            o.y = rv * acc[i][jj + 1] + res.y;
            o.z = rv * acc[i][jj + 2] + res.z;
            o.w = rv * acc[i][jj + 3] + res.w;
            *reinterpret_cast<float4*>(&C[(size_t)row * OUTD_ + col]) = o;
        }
    }
}

// ---------------------------------------------------------------------------
extern "C" void kernel_launch(void* const* d_in, const int* in_sizes, int n_in,
                              void* d_out, int out_size)
{
    const float* x  = (const float*)d_in[0];
    const float* Wk = (const float*)d_in[1];
    const float* bk = (const float*)d_in[2];
    const float* Wq = (const float*)d_in[3];
    const float* bq = (const float*)d_in[4];
    const float* Wv = (const float*)d_in[5];
    const float* bv = (const float*)d_in[6];
    float* out = (float*)d_out;
    (void)in_sizes; (void)n_in; (void)out_size;

    float *pk, *pq, *pv, *ps, *pr;
    cudaGetSymbolAddress((void**)&pk, g_k);
    cudaGetSymbolAddress((void**)&pq, g_q);
    cudaGetSymbolAddress((void**)&pv, g_v);
    cudaGetSymbolAddress((void**)&ps, g_scores);
    cudaGetSymbolAddress((void**)&pr, g_rinv);

    dim3 blk(256);

    // QKV projections: C = x @ W^T + b
    gemm_nt_kernel<<<dim3(KQD_ / 128, G_ / 128), blk>>>(x, Wk, bk, pk, G_, KQD_, IND_);
    gemm_nt_kernel<<<dim3(KQD_ / 128, G_ / 128), blk>>>(x, Wq, bq, pq, G_, KQD_, IND_);
    gemm_nt_kernel<<<dim3(OUTD_ / 128, G_ / 128), blk>>>(x, Wv, bv, pv, G_, OUTD_, IND_);

    // scores = k @ q^T  (no bias)
    gemm_nt_kernel<<<dim3(G_ / 128, G_ / 128), blk>>>(pk, pq, nullptr, ps, G_, G_, KQD_);

    // per-row inverse L2 norm
    rownorm_kernel<<<G_, 256>>>(ps, pr);

    // out = rinv * (scores @ v) + v
    gemm_nn_out_kernel<<<dim3(OUTD_ / 128, G_ / 128), blk>>>(ps, pv, pr, out);
}

// round 3
// speedup vs baseline: 3.3522x; 3.3522x over previous
#include <cuda_runtime.h>
#include <cstdint>
#include <cstddef>
#include <math.h>

#define G_    8192
#define IND_  512
#define KQD_  128
#define OUTD_ 512

// ---------------- scratch (static __device__ = allowed) --------------------
__device__ float g_k[(size_t)G_ * KQD_];
__device__ float g_q[(size_t)G_ * KQD_];
__device__ float g_v[(size_t)G_ * OUTD_];
__device__ float g_scores[(size_t)G_ * G_];
__device__ float g_sumsq[G_];
__device__ float g_rinv[G_];

// ---------------- helpers ---------------------------------------------------
__device__ __forceinline__ uint32_t smem_u32(const void* p) {
    uint32_t a;
    asm("{ .reg .u64 t; cvta.to.shared.u64 t, %1; cvt.u32.u64 %0, t; }"
        : "=r"(a) : "l"(p));
    return a;
}
__device__ __forceinline__ float totf32(float x) {
    uint32_t o;
    asm("cvt.rna.tf32.f32 %0, %1;" : "=r"(o) : "f"(x));
    return __uint_as_float(o);
}
#define CP_ASYNC16(sm, gm) \
    asm volatile("cp.async.cg.shared.global [%0], [%1], 16;" :: "r"(sm), "l"(gm))
#define CP_COMMIT() asm volatile("cp.async.commit_group;" ::: "memory")
#define CP_WAIT(n)  asm volatile("cp.async.wait_group %0;" :: "n"(n) : "memory")

__device__ __forceinline__ void mma_tf32(float* c, const uint32_t* a, const uint32_t* b) {
    asm volatile(
        "mma.sync.aligned.m16n8k8.row.col.f32.tf32.tf32.f32 "
        "{%0,%1,%2,%3}, {%4,%5,%6,%7}, {%8,%9}, {%0,%1,%2,%3};"
        : "+f"(c[0]), "+f"(c[1]), "+f"(c[2]), "+f"(c[3])
        : "r"(a[0]), "r"(a[1]), "r"(a[2]), "r"(a[3]), "r"(b[0]), "r"(b[1]));
}

// ---------------------------------------------------------------------------
// TF32 mma.sync GEMM.  C[M,N]:
//   BLAYOUT 0 (NT): B is [N,K] row-major  ->  C = A @ B^T
//   BLAYOUT 1 (NN): B is [K,N] row-major  ->  C = A @ B
// Block tile 128x128x16, 256 threads, warp tile 64x32, 4-stage cp.async.
// MODE 0: C = rna(acc + bias[col])
// MODE 1: C = rna(acc), sumsq[row] += sum(acc^2) over row
// MODE 2: C = rinv[row]*acc + aux[row*N+col]
// ---------------------------------------------------------------------------
template<int BLAYOUT, int MODE>
__global__ void __launch_bounds__(256)
mma_gemm(const float* __restrict__ A, const float* __restrict__ B,
         const float* __restrict__ aux, const float* __restrict__ rinv,
         float* __restrict__ C, float* __restrict__ sumsq,
         int K, int N)
{
    constexpr int STAGES = 4;
    constexpr int AS = 128 * 20;                          // A stage floats
    constexpr int BS = (BLAYOUT == 0) ? 128 * 20 : 16 * 136;

    extern __shared__ float sm[];
    float* sA = sm;
    float* sB = sm + STAGES * AS;

    const int tid  = threadIdx.x;
    const int warp = tid >> 5;
    const int lane = tid & 31;
    const int gr   = lane >> 2;       // 0..7
    const int tc   = lane & 3;        // 0..3
    const int wm   = (warp & 1) * 64; // warp m offset
    const int wn   = (warp >> 1) * 32;// warp n offset
    const int rowBase = blockIdx.y * 128;
    const int colBase = blockIdx.x * 128;

    float acc[4][4][4];
#pragma unroll
    for (int mi = 0; mi < 4; mi++)
#pragma unroll
        for (int ni = 0; ni < 4; ni++)
#pragma unroll
            for (int r = 0; r < 4; r++) acc[mi][ni][r] = 0.f;

    const int T = K / 16;

    auto load_stage = [&](int it, int buf) {
        const int k0 = it * 16;
        uint32_t dA = smem_u32(sA + buf * AS);
#pragma unroll
        for (int l = 0; l < 2; l++) {
            int c = tid + l * 256;
            int r = c >> 2, ck = (c & 3) * 4;
            CP_ASYNC16(dA + (uint32_t)(r * 20 + ck) * 4,
                       A + (size_t)(rowBase + r) * K + k0 + ck);
        }
        uint32_t dB = smem_u32(sB + buf * BS);
        if (BLAYOUT == 0) {
#pragma unroll
            for (int l = 0; l < 2; l++) {
                int c = tid + l * 256;
                int r = c >> 2, ck = (c & 3) * 4;
                CP_ASYNC16(dB + (uint32_t)(r * 20 + ck) * 4,
                           B + (size_t)(colBase + r) * K + k0 + ck);
            }
        } else {
#pragma unroll
            for (int l = 0; l < 2; l++) {
                int c = tid + l * 256;
                int r = c >> 5, cn = (c & 31) * 4;
                CP_ASYNC16(dB + (uint32_t)(r * 136 + cn) * 4,
                           B + (size_t)(k0 + r) * N + colBase + cn);
            }
        }
        CP_COMMIT();
    };

#pragma unroll
    for (int s = 0; s < STAGES - 1; s++)
        if (s < T) load_stage(s, s);

    for (int i = 0; i < T; i++) {
        const int pf = i + STAGES - 1;
        if (pf < T) load_stage(pf, pf & (STAGES - 1));
        const int rem = T - 1 - i;
        if (rem >= 3)      { CP_WAIT(3); }
        else if (rem == 2) { CP_WAIT(2); }
        else if (rem == 1) { CP_WAIT(1); }
        else               { CP_WAIT(0); }
        __syncthreads();

        const float* cA = sA + (i & (STAGES - 1)) * AS;
        const float* cB = sB + (i & (STAGES - 1)) * BS;
#pragma unroll
        for (int ks = 0; ks < 2; ks++) {
            const int kk = ks * 8;
            uint32_t a[4][4], b[4][2];
#pragma unroll
            for (int mi = 0; mi < 4; mi++) {
                const int r0 = wm + mi * 16;
                a[mi][0] = __float_as_uint(cA[(r0 + gr)     * 20 + kk + tc]);
                a[mi][1] = __float_as_uint(cA[(r0 + 8 + gr) * 20 + kk + tc]);
                a[mi][2] = __float_as_uint(cA[(r0 + gr)     * 20 + kk + tc + 4]);
                a[mi][3] = __float_as_uint(cA[(r0 + 8 + gr) * 20 + kk + tc + 4]);
            }
#pragma unroll
            for (int ni = 0; ni < 4; ni++) {
                const int n0 = wn + ni * 8;
                if (BLAYOUT == 0) {
                    b[ni][0] = __float_as_uint(cB[(n0 + gr) * 20 + kk + tc]);
                    b[ni][1] = __float_as_uint(cB[(n0 + gr) * 20 + kk + tc + 4]);
                } else {
                    b[ni][0] = __float_as_uint(cB[(kk + tc)     * 136 + n0 + gr]);
                    b[ni][1] = __float_as_uint(cB[(kk + tc + 4) * 136 + n0 + gr]);
                }
            }
#pragma unroll
            for (int mi = 0; mi < 4; mi++)
#pragma unroll
                for (int ni = 0; ni < 4; ni++)
                    mma_tf32(acc[mi][ni], a[mi], b[ni]);
        }
        __syncthreads();
    }

    // ---------------- epilogue ----------------
#pragma unroll
    for (int mi = 0; mi < 4; mi++) {
#pragma unroll
        for (int h = 0; h < 2; h++) {
            const int row = rowBase + wm + mi * 16 + h * 8 + gr;
            float rv = 0.f;
            if (MODE == 2) rv = rinv[row];
            float ss = 0.f;
#pragma unroll
            for (int ni = 0; ni < 4; ni++) {
                const int col = colBase + wn + ni * 8 + tc * 2;
                float v0 = acc[mi][ni][h * 2 + 0];
                float v1 = acc[mi][ni][h * 2 + 1];
                float2 o;
                if (MODE == 0) {
                    o.x = totf32(v0 + aux[col]);
                    o.y = totf32(v1 + aux[col + 1]);
                } else if (MODE == 1) {
                    o.x = totf32(v0);
                    o.y = totf32(v1);
                    ss += o.x * o.x + o.y * o.y;
                } else {
                    const float2 res = *reinterpret_cast<const float2*>(
                        aux + (size_t)row * N + col);
                    o.x = rv * v0 + res.x;
                    o.y = rv * v1 + res.y;
                }
                *reinterpret_cast<float2*>(C + (size_t)row * N + col) = o;
            }
            if (MODE == 1) {
                ss += __shfl_xor_sync(0xffffffffu, ss, 1);
                ss += __shfl_xor_sync(0xffffffffu, ss, 2);
                if (tc == 0) atomicAdd(&sumsq[row], ss);
            }
        }
    }
}

// ---------------------------------------------------------------------------
__global__ void rinv_kernel(const float* __restrict__ ss, float* __restrict__ rinv)
{
    int i = blockIdx.x * 256 + threadIdx.x;
    float n = sqrtf(ss[i]);
    rinv[i] = 1.0f / fmaxf(n, 1e-12f);
}

// ---------------------------------------------------------------------------
extern "C" void kernel_launch(void* const* d_in, const int* in_sizes, int n_in,
                              void* d_out, int out_size)
{
    const float* x  = (const float*)d_in[0];
    const float* Wk = (const float*)d_in[1];
    const float* bk = (const float*)d_in[2];
    const float* Wq = (const float*)d_in[3];
    const float* bq = (const float*)d_in[4];
    const float* Wv = (const float*)d_in[5];
    const float* bv = (const float*)d_in[6];
    float* out = (float*)d_out;
    (void)in_sizes; (void)n_in; (void)out_size;

    float *pk, *pq, *pv, *ps, *pss, *pr;
    cudaGetSymbolAddress((void**)&pk,  g_k);
    cudaGetSymbolAddress((void**)&pq,  g_q);
    cudaGetSymbolAddress((void**)&pv,  g_v);
    cudaGetSymbolAddress((void**)&ps,  g_scores);
    cudaGetSymbolAddress((void**)&pss, g_sumsq);
    cudaGetSymbolAddress((void**)&pr,  g_rinv);

    const int smemNT = 4 * (128 * 20 + 128 * 20) * 4;   // 81920 B
    const int smemNN = 4 * (128 * 20 + 16 * 136) * 4;   // 75776 B
    cudaFuncSetAttribute(mma_gemm<0, 0>, cudaFuncAttributeMaxDynamicSharedMemorySize, smemNT);
    cudaFuncSetAttribute(mma_gemm<0, 1>, cudaFuncAttributeMaxDynamicSharedMemorySize, smemNT);
    cudaFuncSetAttribute(mma_gemm<1, 2>, cudaFuncAttributeMaxDynamicSharedMemorySize, smemNN);

    cudaMemsetAsync(pss, 0, G_ * sizeof(float));

    // QKV projections: C = x @ W^T + b  (NT)
    mma_gemm<0, 0><<<dim3(KQD_ / 128, G_ / 128), 256, smemNT>>>(
        x, Wk, bk, nullptr, pk, nullptr, IND_, KQD_);
    mma_gemm<0, 0><<<dim3(KQD_ / 128, G_ / 128), 256, smemNT>>>(
        x, Wq, bq, nullptr, pq, nullptr, IND_, KQD_);
    mma_gemm<0, 0><<<dim3(OUTD_ / 128, G_ / 128), 256, smemNT>>>(
        x, Wv, bv, nullptr, pv, nullptr, IND_, OUTD_);

    // scores = k @ q^T (NT), fused row sum-of-squares
    mma_gemm<0, 1><<<dim3(G_ / 128, G_ / 128), 256, smemNT>>>(
        pk, pq, nullptr, nullptr, ps, pss, KQD_, G_);

    // rinv = 1 / max(||row||, eps)
    rinv_kernel<<<G_ / 256, 256>>>(pss, pr);

    // out = rinv[row] * (S @ V) + V   (NN)
    mma_gemm<1, 2><<<dim3(OUTD_ / 128, G_ / 128), 256, smemNN>>>(
        ps, pv, pv, pr, out, nullptr, G_, OUTD_);
}

// round 4
// speedup vs baseline: 3.6566x; 1.0908x over previous
#include <cuda_runtime.h>
#include <cstdint>
#include <cstddef>
#include <math.h>

#define G_    8192
#define IND_  512
#define KQD_  128
#define OUTD_ 512

// ---------------- scratch (static __device__ = allowed) --------------------
__device__ float g_k[(size_t)G_ * KQD_];
__device__ float g_q[(size_t)G_ * KQD_];
__device__ float g_v[(size_t)G_ * OUTD_];
__device__ float g_vt[(size_t)OUTD_ * G_];
__device__ float g_scores[(size_t)G_ * G_];
__device__ float g_sumsq[G_];
__device__ float g_rinv[G_];

// ---------------- helpers ---------------------------------------------------
__device__ __forceinline__ uint32_t smem_u32(const void* p) {
    uint32_t a;
    asm("{ .reg .u64 t; cvta.to.shared.u64 t, %1; cvt.u32.u64 %0, t; }"
        : "=r"(a) : "l"(p));
    return a;
}
__device__ __forceinline__ float totf32(float x) {
    uint32_t o;
    asm("cvt.rna.tf32.f32 %0, %1;" : "=r"(o) : "f"(x));
    return __uint_as_float(o);
}
#define CP_ASYNC16(sm, gm) \
    asm volatile("cp.async.cg.shared.global [%0], [%1], 16;" :: "r"(sm), "l"(gm))
#define CP_COMMIT() asm volatile("cp.async.commit_group;" ::: "memory")
#define CP_WAIT(n)  asm volatile("cp.async.wait_group %0;" :: "n"(n) : "memory")

#define LDMX4(r0, r1, r2, r3, addr) \
    asm volatile("ldmatrix.sync.aligned.m8n8.x4.shared.b16 {%0,%1,%2,%3}, [%4];" \
                 : "=r"(r0), "=r"(r1), "=r"(r2), "=r"(r3) : "r"(addr))

__device__ __forceinline__ void mma_tf32(float* c, const uint32_t* a, const uint32_t* b) {
    asm volatile(
        "mma.sync.aligned.m16n8k8.row.col.f32.tf32.tf32.f32 "
        "{%0,%1,%2,%3}, {%4,%5,%6,%7}, {%8,%9}, {%0,%1,%2,%3};"
        : "+f"(c[0]), "+f"(c[1]), "+f"(c[2]), "+f"(c[3])
        : "r"(a[0]), "r"(a[1]), "r"(a[2]), "r"(a[3]), "r"(b[0]), "r"(b[1]));
}

// ---------------------------------------------------------------------------
// TF32 mma.sync GEMM-NT:  C[M,N] = A[M,K] @ B[N,K]^T   (both row-major)
// Block 128x128x16, 256 threads, warp tile 64x32 (2x4 warp grid),
// 4-stage cp.async, ldmatrix.x4 fragment loads, 1 syncthreads per iter.
// MODE 0: C = rna(acc + bias[col])                (aux = bias)
// MODE 1: C = rna(acc), sumsq[row] += row sumsq   (scores)
// MODE 2: C = rinv[row]*acc + aux[row*N+col]      (final, aux = V row-major)
// ---------------------------------------------------------------------------
template<int MODE>
__global__ void __launch_bounds__(256, 2)
mma_gemm(const float* __restrict__ A, const float* __restrict__ B,
         const float* __restrict__ aux, const float* __restrict__ rinv,
         float* __restrict__ C, float* __restrict__ sumsq,
         int K, int N)
{
    constexpr int STAGES = 4;
    constexpr int AS = 128 * 20;          // floats per A stage (row stride 20)
    constexpr int BS = 128 * 20;

    extern __shared__ float sm[];
    float* sA = sm;
    float* sB = sm + STAGES * AS;
    const uint32_t sAu = smem_u32(sA);
    const uint32_t sBu = smem_u32(sB);

    const int tid  = threadIdx.x;
    const int warp = tid >> 5;
    const int lane = tid & 31;
    const int gr   = lane >> 2;        // 0..7
    const int tc   = lane & 3;         // 0..3
    const int wm   = (warp & 1) * 64;  // warp m offset
    const int wn   = (warp >> 1) * 32; // warp n offset
    const int rowBase = blockIdx.y * 128;
    const int colBase = blockIdx.x * 128;

    // per-thread ldmatrix row/col selects
    const int aRow = wm + (lane & 15);
    const int aCol = (lane >> 4) << 2;                       // 0 or 4
    const int bRow = wn + ((lane >> 4) << 3) + (lane & 7);   // +8 for upper tile pair
    const int bCol = ((lane >> 3) & 1) << 2;                 // 0 or 4

    float acc[4][4][4];
#pragma unroll
    for (int mi = 0; mi < 4; mi++)
#pragma unroll
        for (int ni = 0; ni < 4; ni++)
#pragma unroll
            for (int r = 0; r < 4; r++) acc[mi][ni][r] = 0.f;

    const int T = K / 16;

    auto load_stage = [&](int it, int buf) {
        const int k0 = it * 16;
#pragma unroll
        for (int l = 0; l < 2; l++) {
            int c = tid + l * 256;
            int r = c >> 2, ck = (c & 3) * 4;
            CP_ASYNC16(sAu + (uint32_t)(buf * AS + r * 20 + ck) * 4,
                       A + (size_t)(rowBase + r) * K + k0 + ck);
        }
#pragma unroll
        for (int l = 0; l < 2; l++) {
            int c = tid + l * 256;
            int r = c >> 2, ck = (c & 3) * 4;
            CP_ASYNC16(sBu + (uint32_t)(buf * BS + r * 20 + ck) * 4,
                       B + (size_t)(colBase + r) * K + k0 + ck);
        }
        CP_COMMIT();
    };

#pragma unroll
    for (int s = 0; s < STAGES - 1; s++)
        if (s < T) load_stage(s, s);

    for (int i = 0; i < T; i++) {
        const int rem = T - 1 - i;
        if (rem >= 2)      { CP_WAIT(2); }
        else if (rem == 1) { CP_WAIT(1); }
        else               { CP_WAIT(0); }
        __syncthreads();
        if (i + STAGES - 1 < T) load_stage(i + STAGES - 1, (i + STAGES - 1) & (STAGES - 1));

        const uint32_t cA = sAu + (uint32_t)((i & (STAGES - 1)) * AS) * 4;
        const uint32_t cB = sBu + (uint32_t)((i & (STAGES - 1)) * BS) * 4;
#pragma unroll
        for (int ks = 0; ks < 2; ks++) {
            const int kk = ks * 8;
            uint32_t a[4][4], b[4][2];
#pragma unroll
            for (int mi = 0; mi < 4; mi++) {
                uint32_t ad = cA + (uint32_t)((aRow + mi * 16) * 20 + kk + aCol) * 4;
                LDMX4(a[mi][0], a[mi][1], a[mi][2], a[mi][3], ad);
            }
#pragma unroll
            for (int p = 0; p < 2; p++) {
                uint32_t bd = cB + (uint32_t)((bRow + p * 16) * 20 + kk + bCol) * 4;
                LDMX4(b[2 * p][0], b[2 * p][1], b[2 * p + 1][0], b[2 * p + 1][1], bd);
            }
#pragma unroll
            for (int mi = 0; mi < 4; mi++)
#pragma unroll
                for (int ni = 0; ni < 4; ni++)
                    mma_tf32(acc[mi][ni], a[mi], b[ni]);
        }
    }

    // ---------------- epilogue ----------------
#pragma unroll
    for (int mi = 0; mi < 4; mi++) {
#pragma unroll
        for (int h = 0; h < 2; h++) {
            const int row = rowBase + wm + mi * 16 + h * 8 + gr;
            float rv = 0.f;
            if (MODE == 2) rv = rinv[row];
            float ss = 0.f;
#pragma unroll
            for (int ni = 0; ni < 4; ni++) {
                const int col = colBase + wn + ni * 8 + tc * 2;
                float v0 = acc[mi][ni][h * 2 + 0];
                float v1 = acc[mi][ni][h * 2 + 1];
                float2 o;
                if (MODE == 0) {
                    o.x = totf32(v0 + aux[col]);
                    o.y = totf32(v1 + aux[col + 1]);
                } else if (MODE == 1) {
                    o.x = totf32(v0);
                    o.y = totf32(v1);
                    ss += o.x * o.x + o.y * o.y;
                } else {
                    const float2 res = *reinterpret_cast<const float2*>(
                        aux + (size_t)row * N + col);
                    o.x = rv * v0 + res.x;
                    o.y = rv * v1 + res.y;
                }
                *reinterpret_cast<float2*>(C + (size_t)row * N + col) = o;
            }
            if (MODE == 1) {
                ss += __shfl_xor_sync(0xffffffffu, ss, 1);
                ss += __shfl_xor_sync(0xffffffffu, ss, 2);
                if (tc == 0) atomicAdd(&sumsq[row], ss);
            }
        }
    }
}

// ---------------------------------------------------------------------------
__global__ void transpose_k(const float* __restrict__ in, float* __restrict__ out)
{
    __shared__ float t[32][33];
    int x  = blockIdx.x * 32 + threadIdx.x;   // col of in  (0..511)
    int y0 = blockIdx.y * 32;                 // row of in  (0..8191)
#pragma unroll
    for (int i = threadIdx.y; i < 32; i += 8)
        t[i][threadIdx.x] = in[(size_t)(y0 + i) * OUTD_ + x];
    __syncthreads();
    int ox  = y0 + threadIdx.x;               // col of out (g index)
    int oy0 = blockIdx.x * 32;                // row of out (o index)
#pragma unroll
    for (int i = threadIdx.y; i < 32; i += 8)
        out[(size_t)(oy0 + i) * G_ + ox] = t[threadIdx.x][i];
}

__global__ void rinv_kernel(const float* __restrict__ ss, float* __restrict__ rinv)
{
    int i = blockIdx.x * 256 + threadIdx.x;
    float n = sqrtf(ss[i]);
    rinv[i] = 1.0f / fmaxf(n, 1e-12f);
}

// ---------------------------------------------------------------------------
extern "C" void kernel_launch(void* const* d_in, const int* in_sizes, int n_in,
                              void* d_out, int out_size)
{
    const float* x  = (const float*)d_in[0];
    const float* Wk = (const float*)d_in[1];
    const float* bk = (const float*)d_in[2];
    const float* Wq = (const float*)d_in[3];
    const float* bq = (const float*)d_in[4];
    const float* Wv = (const float*)d_in[5];
    const float* bv = (const float*)d_in[6];
    float* out = (float*)d_out;
    (void)in_sizes; (void)n_in; (void)out_size;

    float *pk, *pq, *pv, *pvt, *ps, *pss, *pr;
    cudaGetSymbolAddress((void**)&pk,  g_k);
    cudaGetSymbolAddress((void**)&pq,  g_q);
    cudaGetSymbolAddress((void**)&pv,  g_v);
    cudaGetSymbolAddress((void**)&pvt, g_vt);
    cudaGetSymbolAddress((void**)&ps,  g_scores);
    cudaGetSymbolAddress((void**)&pss, g_sumsq);
    cudaGetSymbolAddress((void**)&pr,  g_rinv);

    const int smemB = 4 * (128 * 20 + 128 * 20) * 4;   // 81920 B
    cudaFuncSetAttribute(mma_gemm<0>, cudaFuncAttributeMaxDynamicSharedMemorySize, smemB);
    cudaFuncSetAttribute(mma_gemm<1>, cudaFuncAttributeMaxDynamicSharedMemorySize, smemB);
    cudaFuncSetAttribute(mma_gemm<2>, cudaFuncAttributeMaxDynamicSharedMemorySize, smemB);

    cudaMemsetAsync(pss, 0, G_ * sizeof(float));

    // QKV projections: C = x @ W^T + b  (NT)
    mma_gemm<0><<<dim3(KQD_ / 128, G_ / 128), 256, smemB>>>(
        x, Wk, bk, nullptr, pk, nullptr, IND_, KQD_);
    mma_gemm<0><<<dim3(KQD_ / 128, G_ / 128), 256, smemB>>>(
        x, Wq, bq, nullptr, pq, nullptr, IND_, KQD_);
    mma_gemm<0><<<dim3(OUTD_ / 128, G_ / 128), 256, smemB>>>(
        x, Wv, bv, nullptr, pv, nullptr, IND_, OUTD_);

    // V^T so the big GEMM is NT (ldmatrix-friendly)
    transpose_k<<<dim3(OUTD_ / 32, G_ / 32), dim3(32, 8)>>>(pv, pvt);

    // scores = k @ q^T (NT), fused row sum-of-squares
    mma_gemm<1><<<dim3(G_ / 128, G_ / 128), 256, smemB>>>(
        pk, pq, nullptr, nullptr, ps, pss, KQD_, G_);

    // rinv = 1 / max(||row||, eps)
    rinv_kernel<<<G_ / 256, 256>>>(pss, pr);

    // out = rinv[row] * (S @ V) + V   (NT against V^T)
    mma_gemm<2><<<dim3(OUTD_ / 128, G_ / 128), 256, smemB>>>(
        ps, pvt, pv, pr, out, nullptr, G_, OUTD_);
}